// round 11
// baseline (speedup 1.0000x reference)
#include <cuda_runtime.h>
#include <math.h>
#include <stdint.h>

// Problem constants
#define SEQ   512
#define BATCH 64
#define HID   1024
#define NIN   512
#define NOUT  512
#define BH    (BATCH * HID)
#define FCTA  64          // fused recurrence grid: 8 col-chunks x 8 k-chunks

// Scratch (device globals). Layout of xi/h: [s][b][h]
__device__ float g_xi[(size_t)SEQ * BATCH * HID];
__device__ float g_h [(size_t)SEQ * BATCH * HID];
// Triple-buffered partials: [buf 3][q 8][64 rows][HID cols]
__device__ float g_part3[(size_t)3 * 8 * 64 * HID];

// Dataflow counters: grp[a] counts partial-writes by the 8 CTAs with jt=a
__device__ unsigned g_grp[8 * 32];    // padded 128B apart

__global__ void reset_barriers()
{
    if (threadIdx.x < 8) g_grp[threadIdx.x << 5] = 0;
}

__device__ __forceinline__ unsigned ld_acq(const unsigned* p)
{
    unsigned v;
    asm volatile("ld.acquire.gpu.global.u32 %0, [%1];" : "=r"(v) : "l"(p));
    return v;
}
__device__ __forceinline__ void arrive(unsigned* p)
{
    asm volatile("red.release.gpu.global.add.u32 [%0], 1;" :: "l"(p) : "memory");
}
__device__ __forceinline__ float tf32_hi(float a)
{
    uint32_t u;
    asm("cvt.rna.tf32.f32 %0, %1;" : "=r"(u) : "f"(a));
    return __uint_as_float(u);
}

// mma.sync m16n8k8 tf32 (fragment mapping validated rounds 9-10)
#define MMA_TF32(c, a, b)                                                   \
    asm volatile("mma.sync.aligned.m16n8k8.row.col.f32.tf32.tf32.f32 "      \
        "{%0,%1,%2,%3}, {%4,%5,%6,%7}, {%8,%9}, {%0,%1,%2,%3};"             \
        : "+f"((c)[0]), "+f"((c)[1]), "+f"((c)[2]), "+f"((c)[3])            \
        : "r"((a)[0]), "r"((a)[1]), "r"((a)[2]), "r"((a)[3]),               \
          "r"((b)[0]), "r"((b)[1]))

// ---------------------------------------------------------------------------
// 128x128x8 fp32 SGEMM with bias + output-row permutation (proven).
// PERM=1: A row m=(b*512+s) -> C row (s*64+b)   [GEMM1: x->xi]
// PERM=2: A row m=(s*64+b)  -> C row (b*512+s)  [GEMM3: h->y]
// ---------------------------------------------------------------------------
template<int K, int N, int PERM>
__global__ __launch_bounds__(256, 2) void gemm128(
    const float* __restrict__ A, const float* __restrict__ Bm,
    const float* __restrict__ bias, float* __restrict__ C)
{
    __shared__ float As[8][132];
    __shared__ float Bs[8][128];

    const int tid = threadIdx.x;
    const int tx = tid & 15, ty = tid >> 4;
    const int row0 = blockIdx.y * 128, col0 = blockIdx.x * 128;

    const int a_r = tid >> 1, a_k = (tid & 1) << 2;
    const int b_k = tid >> 5, b_c = (tid & 31) << 2;

    const float* Ap = A + (size_t)(row0 + a_r) * K + a_k;
    const float* Bp = Bm + (size_t)b_k * N + col0 + b_c;

    float4 ar = *(const float4*)Ap;
    float4 br = *(const float4*)Bp;

    float acc[8][8] = {};

    for (int k0 = 0; k0 < K; k0 += 8) {
        As[a_k + 0][a_r] = ar.x;
        As[a_k + 1][a_r] = ar.y;
        As[a_k + 2][a_r] = ar.z;
        As[a_k + 3][a_r] = ar.w;
        *(float4*)&Bs[b_k][b_c] = br;
        __syncthreads();
        if (k0 + 8 < K) {
            ar = *(const float4*)(Ap + k0 + 8);
            br = *(const float4*)(Bp + (size_t)(k0 + 8) * N);
        }
#pragma unroll
        for (int kk = 0; kk < 8; kk++) {
            float4 a0 = *(const float4*)&As[kk][ty << 2];
            float4 a1 = *(const float4*)&As[kk][(ty << 2) + 64];
            float4 b0 = *(const float4*)&Bs[kk][tx << 2];
            float4 b1 = *(const float4*)&Bs[kk][(tx << 2) + 64];
            float av[8] = {a0.x, a0.y, a0.z, a0.w, a1.x, a1.y, a1.z, a1.w};
            float bv[8] = {b0.x, b0.y, b0.z, b0.w, b1.x, b1.y, b1.z, b1.w};
#pragma unroll
            for (int i = 0; i < 8; i++)
#pragma unroll
                for (int j = 0; j < 8; j++)
                    acc[i][j] = fmaf(av[i], bv[j], acc[i][j]);
        }
        __syncthreads();
    }

    float4 bb0 = *(const float4*)&bias[col0 + (tx << 2)];
    float4 bb1 = *(const float4*)&bias[col0 + (tx << 2) + 64];
#pragma unroll
    for (int i = 0; i < 8; i++) {
        const int mloc = (i < 4) ? ((ty << 2) + i) : ((ty << 2) + i + 60);
        const int m = row0 + mloc;
        size_t r;
        if (PERM == 1)      r = (size_t)((m & 511) * 64 + (m >> 9));
        else if (PERM == 2) r = (size_t)((m & 63) * 512 + (m >> 6));
        else                r = (size_t)m;
        float* Cr = C + r * N + col0;
        float4 o0 = make_float4(acc[i][0] + bb0.x, acc[i][1] + bb0.y,
                                acc[i][2] + bb0.z, acc[i][3] + bb0.w);
        float4 o1 = make_float4(acc[i][4] + bb1.x, acc[i][5] + bb1.y,
                                acc[i][6] + bb1.z, acc[i][7] + bb1.w);
        *(float4*)(Cr + (tx << 2)) = o0;
        *(float4*)(Cr + (tx << 2) + 64) = o1;
    }
}

// ---------------------------------------------------------------------------
// Fused one-hop recurrence. 64 CTAs: a = bx&7 (cols 128a), b = bx>>3 (k 128b).
// Round r (1..511): [wait grp[b] >= 8(r-1)] -> reduce h(r-1) k-chunk from
// xi + partials (redundant, tanh+relu, to smem; CTA a==b also writes g_h) ->
// 3xTF32 MMA vs resident Wh fragments -> store partials buf[r%3] -> arrive
// grp[a]. Final: designated CTAs reduce h(511).
// ---------------------------------------------------------------------------
#define FR_SMEM (131072 + 64 * 132 * 4)     // Bfrag + hs[64][132]

__global__ __launch_bounds__(256) void rnn_fused(const float* __restrict__ Wh)
{
    extern __shared__ float dsm[];
    float4* Bfrag = (float4*)dsm;            // [ks 16][j8 16][lane 32] float4
    float*  hs    = dsm + 32768;             // hs[64][132]

    const int tid  = threadIdx.x;
    const int lane = tid & 31, w = tid >> 5;
    const int gid  = lane >> 2, tig = lane & 3;
    const int a = blockIdx.x & 7, b = blockIdx.x >> 3;
    const int col0 = a << 7, kbase = b << 7;
    const int m0 = (w & 3) << 4;             // warp row base (0..48)
    const int nh = (w >> 2) << 3;            // warp j8-tile base (0 or 8)

    // One-time: fragment-ordered hi/lo Wh slice rows[kbase..+128) x cols[col0..+128)
    for (int i = tid; i < 16 * 16 * 32; i += 256) {
        const int l = i & 31, j8 = (i >> 5) & 15, ks = i >> 9;
        const int tg = l & 3, g = l >> 2;
        const int kr = kbase + ks * 8 + tg;
        const int nc = col0 + j8 * 8 + g;
        float b0 = Wh[(size_t)kr * HID + nc];
        float b1 = Wh[(size_t)(kr + 4) * HID + nc];
        float b0h = tf32_hi(b0), b1h = tf32_hi(b1);
        Bfrag[i] = make_float4(b0h, b1h, b0 - b0h, b1 - b1h);
    }

    for (int r = 1; r < SEQ; r++) {
        // ---- one-hop wait: partials of round r-1 for k-chunk b ready ----
        if (r > 1) {
            if (tid == 0) {
                const unsigned target = 8u * (unsigned)(r - 1);
                while (ld_acq(&g_grp[b << 5]) < target) {}
            }
        }
        __syncthreads();   // also orders Bfrag (r==1) / hs reuse

        // ---- reduce h(r-1)[:, kbase..+128) from xi (+partials), tanh, relu ----
        {
            const float* xi = g_xi + (size_t)(r - 1) * BH;
            const int p1 = (r - 1) % 3;
#pragma unroll
            for (int i = 0; i < 8; i++) {
                const int idx = tid + (i << 8);          // 0..2047 float4 slots
                const int row = idx >> 5, c4 = idx & 31;
                const size_t go = (size_t)row * HID + kbase + (c4 << 2);
                float4 v = *(const float4*)&xi[go];
                if (r > 1) {
#pragma unroll
                    for (int q = 0; q < 8; q++) {
                        const float4 p = *(const float4*)
                            &g_part3[((size_t)(p1 * 8 + q) * 64 + row) * HID
                                     + kbase + (c4 << 2)];
                        v.x += p.x; v.y += p.y; v.z += p.z; v.w += p.w;
                    }
                }
                v.x = fmaxf(tanhf(v.x), 0.0f);
                v.y = fmaxf(tanhf(v.y), 0.0f);
                v.z = fmaxf(tanhf(v.z), 0.0f);
                v.w = fmaxf(tanhf(v.w), 0.0f);
                *(float4*)&hs[row * 132 + (c4 << 2)] = v;
                if (a == b)
                    *(float4*)&g_h[(size_t)(r - 1) * BH + go] = v;
            }
        }
        __syncthreads();

        // ---- 3xTF32 MMA: warp computes rows [m0..m0+16) x cols 64-half ----
        float c[8][4] = {};
#pragma unroll
        for (int ks = 0; ks < 16; ks++) {
            const int kb = (ks << 3) + tig;
            float a0 = hs[(m0 + gid) * 132 + kb];
            float a1 = hs[(m0 + 8 + gid) * 132 + kb];
            float a2 = hs[(m0 + gid) * 132 + kb + 4];
            float a3 = hs[(m0 + 8 + gid) * 132 + kb + 4];
            uint32_t ah[4], al[4];
            float h;
            h = tf32_hi(a0); ah[0] = __float_as_uint(h); al[0] = __float_as_uint(a0 - h);
            h = tf32_hi(a1); ah[1] = __float_as_uint(h); al[1] = __float_as_uint(a1 - h);
            h = tf32_hi(a2); ah[2] = __float_as_uint(h); al[2] = __float_as_uint(a2 - h);
            h = tf32_hi(a3); ah[3] = __float_as_uint(h); al[3] = __float_as_uint(a3 - h);

            const float4* bp = Bfrag + ((size_t)((ks << 4) + nh)) * 32 + lane;
#pragma unroll
            for (int j = 0; j < 8; j++) {
                float4 bf = bp[j * 32];
                uint32_t bh[2] = {__float_as_uint(bf.x), __float_as_uint(bf.y)};
                uint32_t bl[2] = {__float_as_uint(bf.z), __float_as_uint(bf.w)};
                MMA_TF32(c[j], ah, bh);
                MMA_TF32(c[j], ah, bl);
                MMA_TF32(c[j], al, bh);
            }
        }

        // ---- store partials to buf[r%3], slice q=b, cols [col0..+128) ----
        {
            float* pd = &g_part3[(size_t)((r % 3) * 8 + b) * (64 * HID)];
#pragma unroll
            for (int j = 0; j < 8; j++) {
                float* pp = pd + (size_t)(m0 + gid) * HID + col0
                            + ((nh + j) << 3) + (tig << 1);
                *(float2*)pp = make_float2(c[j][0], c[j][1]);
                *(float2*)(pp + 8 * HID) = make_float2(c[j][2], c[j][3]);
            }
        }
        __syncthreads();
        if (tid == 0) arrive(&g_grp[a << 5]);
    }

    // ---- final: designated CTAs reduce h(511) and write it for GEMM3 ----
    if (a == b) {
        if (tid == 0) {
            const unsigned target = 8u * (unsigned)(SEQ - 1);
            while (ld_acq(&g_grp[b << 5]) < target) {}
        }
        __syncthreads();
        const float* xi = g_xi + (size_t)(SEQ - 1) * BH;
        const int p1 = (SEQ - 1) % 3;
#pragma unroll
        for (int i = 0; i < 8; i++) {
            const int idx = tid + (i << 8);
            const int row = idx >> 5, c4 = idx & 31;
            const size_t go = (size_t)row * HID + kbase + (c4 << 2);
            float4 v = *(const float4*)&xi[go];
#pragma unroll
            for (int q = 0; q < 8; q++) {
                const float4 p = *(const float4*)
                    &g_part3[((size_t)(p1 * 8 + q) * 64 + row) * HID
                             + kbase + (c4 << 2)];
                v.x += p.x; v.y += p.y; v.z += p.z; v.w += p.w;
            }
            v.x = fmaxf(tanhf(v.x), 0.0f);
            v.y = fmaxf(tanhf(v.y), 0.0f);
            v.z = fmaxf(tanhf(v.z), 0.0f);
            v.w = fmaxf(tanhf(v.w), 0.0f);
            *(float4*)&g_h[(size_t)(SEQ - 1) * BH + go] = v;
        }
    }
}

// ---------------------------------------------------------------------------
extern "C" void kernel_launch(void* const* d_in, const int* in_sizes, int n_in,
                              void* d_out, int out_size)
{
    const float* x  = (const float*)d_in[0];
    const float* Wi = (const float*)d_in[1];
    const float* bi = (const float*)d_in[2];
    const float* Wh = (const float*)d_in[3];
    const float* Wo = (const float*)d_in[4];
    const float* bo = (const float*)d_in[5];
    float* out = (float*)d_out;

    void* p;
    cudaGetSymbolAddress(&p, g_xi);
    float* xi = (float*)p;
    cudaGetSymbolAddress(&p, g_h);
    float* hh = (float*)p;

    cudaFuncSetAttribute(rnn_fused,
                         cudaFuncAttributeMaxDynamicSharedMemorySize, FR_SMEM);

    // 0) zero dataflow counters so every graph replay starts clean
    reset_barriers<<<1, 32>>>();

    // 1) xi[s][b][h] = x @ Wi + bi   (fp32, ~roofline)
    gemm128<NIN, HID, 1><<<dim3(HID / 128, (BATCH * SEQ) / 128), 256>>>(x, Wi, bi, xi);

    // 2) whole recurrence: one persistent kernel, ONE sync hop per step
    rnn_fused<<<FCTA, 256, FR_SMEM>>>(Wh);

    // 3) y[b][s][o] = h @ Wo + bo    (fp32, ~roofline)
    gemm128<HID, NOUT, 2><<<dim3(NOUT / 128, (BATCH * SEQ) / 128), 256>>>(hh, Wo, bo, out);
}